// round 12
// baseline (speedup 1.0000x reference)
#include <cuda_runtime.h>

#define NN 50000
#define EE 800000
#define FF 64
#define GG 128
#define CAP 96   // per-node bucket capacity (Poisson λ=16 -> P(deg>96) ~ 0)

// ---------------- device scratch (static allocation only) --------------------
// Zero-initialized at module load; k_final re-zeroes mutable state after every
// call so each graph replay starts clean (deterministic).
__device__ int   g_cur[NN];                 // per-node fill cursor == in-degree
__device__ int   g_src[NN * CAP];           // bucketed CSR: sources per dst
__device__ __align__(16) float g_agg[NN * FF];
__device__ __align__(16) float g_h1[NN * FF];
__device__ float g_pool[GG];
__device__ float g_cnt[GG];
__device__ int   g_b64;

__device__ __forceinline__ int loadIdx(const int* p, long long i, int is64) {
    return is64 ? p[2 * i] : p[(int)i];
}

__device__ __forceinline__ int detect_ei64(const int* ei) {
    int or_odd = 0;
    #pragma unroll
    for (int k = 0; k < 8; k++) or_odd |= ei[2 * k + 1];
    return (or_odd == 0) ? 1 : 0;
}

// ---------------- fill: bucketed CSR build; block 0 also does batch work -----
__global__ void k_fill(const int* ei, const int* batch) {
    int is64 = detect_ei64(ei);
    int e = blockIdx.x * blockDim.x + threadIdx.x;
    if (e < EE) {
        int s = loadIdx(ei, e, is64);
        int d = loadIdx(ei, (long long)EE + e, is64);
        int pos = atomicAdd(&g_cur[d], 1);
        if (pos < CAP) g_src[d * CAP + pos] = s;   // clamp guards OOB
    }
    if (blockIdx.x == 0) {
        int t = threadIdx.x;
        __shared__ int s_b64;
        if (t == 0) {
            int or_tail = 0;
            #pragma unroll
            for (int k = 0; k < 8; k++) or_tail |= batch[NN - 1 - 2 * k];
            s_b64 = (or_tail == 0) ? 1 : 0;
            g_b64 = s_b64;
        }
        __syncthreads();
        int isb = s_b64;
        if (t < GG) {
            int lo0 = 0, hi0 = NN, lo1 = 0, hi1 = NN;
            while (lo0 < hi0) { int m = (lo0 + hi0) >> 1; if (loadIdx(batch, m, isb) < t)     lo0 = m + 1; else hi0 = m; }
            while (lo1 < hi1) { int m = (lo1 + hi1) >> 1; if (loadIdx(batch, m, isb) < t + 1) lo1 = m + 1; else hi1 = m; }
            g_cnt[t] = (float)(lo1 - lo0);
        }
    }
}

// gather: TWO nodes per warp. Each half-warp (16 lanes x float4 = 256B row)
// owns one node. Per warp step both halves consume one edge each:
// 2 SHFL + 1 LDG.128 + 4 FMA  (3.5 instrs/edge).
// agg[d] = dinv[d] * ( dinv[d]*feat[d] + sum_e dinv[src]*feat[src] ),
// dinv[n] = rsqrt(deg[n]+1) computed on the fly from g_cur.
template <int LAYER>
__global__ void k_gather(const float* __restrict__ featArg) {
    const float4* feat4 = reinterpret_cast<const float4*>(
        (LAYER == 0) ? featArg : (const float*)g_h1);
    int warp = (blockIdx.x * blockDim.x + threadIdx.x) >> 5;
    int nodeA = warp * 2;
    if (nodeA >= NN) return;
    int lane = threadIdx.x & 31;
    int half = lane >> 4;
    int slot = lane & 15;
    int myNode = nodeA + half;          // NN even, so nodeA+1 < NN always

    int degA = min(g_cur[nodeA], CAP);
    int degB = min(g_cur[nodeA + 1], CAP);
    int myDeg = half ? degB : degA;
    int maxDeg = max(degA, degB);

    float dd = rsqrtf((float)(myDeg + 1));
    float4 v = feat4[myNode * 16 + slot];
    float4 acc = make_float4(v.x * dd, v.y * dd, v.z * dd, v.w * dd);

    int myRow = myNode * CAP;
    for (int base = 0; base < maxDeg; base += 16) {
        // stage: each half loads up to 16 of its node's edges (slot-indexed)
        int idx = base + slot;
        int sl = myNode; float wl = 0.f;
        if (idx < myDeg) {
            sl = __ldg(&g_src[myRow + idx]);
            wl = rsqrtf((float)(__ldg(&g_cur[sl]) + 1));
        }
        int cnt = min(maxDeg - base, 16);
        int lbase = half << 4;
        #pragma unroll 4
        for (int j = 0; j < cnt; j++) {
            int   s = __shfl_sync(0xffffffffu, sl, lbase + j);
            float w = __shfl_sync(0xffffffffu, wl, lbase + j);
            float4 f = feat4[s * 16 + slot];
            acc.x = fmaf(w, f.x, acc.x);
            acc.y = fmaf(w, f.y, acc.y);
            acc.z = fmaf(w, f.z, acc.z);
            acc.w = fmaf(w, f.w, acc.w);
        }
    }
    reinterpret_cast<float4*>(g_agg)[myNode * 16 + slot] =
        make_float4(acc.x * dd, acc.y * dd, acc.z * dd, acc.w * dd);
}

// h1 = relu(agg @ W1 + b1),  W1: [64,64]
__global__ void k_gemm1(const float* __restrict__ W1, const float* __restrict__ b1) {
    __shared__ __align__(16) float Ws[FF * FF];
    __shared__ __align__(16) float bs[FF];
    int tid = threadIdx.x;
    for (int k = tid; k < FF * FF; k += blockDim.x) Ws[k] = W1[k];
    if (tid < FF) bs[tid] = b1[tid];
    __syncthreads();

    int i = blockIdx.x * blockDim.x + tid;
    if (i >= NN) return;

    float a[FF];
    #pragma unroll
    for (int k4 = 0; k4 < FF / 4; k4++) {
        float4 v = reinterpret_cast<const float4*>(g_agg)[i * (FF / 4) + k4];
        a[4 * k4 + 0] = v.x; a[4 * k4 + 1] = v.y; a[4 * k4 + 2] = v.z; a[4 * k4 + 3] = v.w;
    }
    const float4* Ws4 = reinterpret_cast<const float4*>(Ws);
    const float4* bs4 = reinterpret_cast<const float4*>(bs);
    #pragma unroll
    for (int j4 = 0; j4 < FF / 4; j4++) {
        float4 acc = bs4[j4];
        #pragma unroll 16
        for (int k = 0; k < FF; k++) {
            float4 w = Ws4[k * (FF / 4) + j4];
            acc.x = fmaf(a[k], w.x, acc.x);
            acc.y = fmaf(a[k], w.y, acc.y);
            acc.z = fmaf(a[k], w.z, acc.z);
            acc.w = fmaf(a[k], w.w, acc.w);
        }
        acc.x = fmaxf(acc.x, 0.0f); acc.y = fmaxf(acc.y, 0.0f);
        acc.z = fmaxf(acc.z, 0.0f); acc.w = fmaxf(acc.w, 0.0f);
        reinterpret_cast<float4*>(g_h1)[i * (FF / 4) + j4] = acc;
    }
}

// fused: s_i = relu(agg_i @ W2 + b2) . fcW ; pool[batch[i]] += s_i (warp-aggregated)
__global__ void k_gemm2_fused(const float* __restrict__ W2, const float* __restrict__ b2,
                              const float* __restrict__ fcW, const int* __restrict__ batch) {
    __shared__ __align__(16) float Ws[FF * 2 * FF];   // 32 KB
    __shared__ __align__(16) float bs[2 * FF];
    __shared__ __align__(16) float fs[2 * FF];
    int tid = threadIdx.x;
    for (int k = tid; k < FF * 2 * FF; k += blockDim.x) Ws[k] = W2[k];
    for (int k = tid; k < 2 * FF; k += blockDim.x) { bs[k] = b2[k]; fs[k] = fcW[k]; }
    __syncthreads();

    int i = blockIdx.x * blockDim.x + tid;
    float s = 0.0f;
    int g = -1;
    if (i < NN) {
        g = loadIdx(batch, i, g_b64);
        float a[FF];
        #pragma unroll
        for (int k4 = 0; k4 < FF / 4; k4++) {
            float4 v = reinterpret_cast<const float4*>(g_agg)[i * (FF / 4) + k4];
            a[4 * k4 + 0] = v.x; a[4 * k4 + 1] = v.y; a[4 * k4 + 2] = v.z; a[4 * k4 + 3] = v.w;
        }
        const float4* Ws4 = reinterpret_cast<const float4*>(Ws);
        const float4* bs4 = reinterpret_cast<const float4*>(bs);
        const float4* fs4 = reinterpret_cast<const float4*>(fs);
        #pragma unroll 4
        for (int j4 = 0; j4 < (2 * FF) / 4; j4++) {
            float4 acc = bs4[j4];
            #pragma unroll 16
            for (int k = 0; k < FF; k++) {
                float4 w = Ws4[k * (2 * FF / 4) + j4];
                acc.x = fmaf(a[k], w.x, acc.x);
                acc.y = fmaf(a[k], w.y, acc.y);
                acc.z = fmaf(a[k], w.z, acc.z);
                acc.w = fmaf(a[k], w.w, acc.w);
            }
            acc.x = fmaxf(acc.x, 0.0f); acc.y = fmaxf(acc.y, 0.0f);
            acc.z = fmaxf(acc.z, 0.0f); acc.w = fmaxf(acc.w, 0.0f);
            float4 f = fs4[j4];
            s = fmaf(acc.x, f.x, s); s = fmaf(acc.y, f.y, s);
            s = fmaf(acc.z, f.z, s); s = fmaf(acc.w, f.w, s);
        }
    }
    unsigned lane = threadIdx.x & 31u;
    #pragma unroll
    for (int off = 1; off < 32; off <<= 1) {
        float o = __shfl_down_sync(0xffffffffu, s, off);
        int   og = __shfl_down_sync(0xffffffffu, g, off);
        if (lane + off < 32 && og == g) s += o;
    }
    int gprev = __shfl_up_sync(0xffffffffu, g, 1);
    if (g >= 0 && (lane == 0 || gprev != g)) atomicAdd(&g_pool[g], s);
}

// final: block 0 writes output; ALL blocks reset mutable state for next replay
__global__ void k_final(float* __restrict__ out, const float* __restrict__ fcb) {
    int i = blockIdx.x * blockDim.x + threadIdx.x;
    if (blockIdx.x == 0 && threadIdx.x < GG) {
        int t = threadIdx.x;
        out[t] = g_pool[t] / fmaxf(g_cnt[t], 1.0f) + fcb[0];
        g_pool[t] = 0.0f;   // after read
    }
    if (i < NN) g_cur[i] = 0;
}

// ---------------- launch ------------------------------------------------------
extern "C" void kernel_launch(void* const* d_in, const int* in_sizes, int n_in,
                              void* d_out, int out_size) {
    const float* x     = (const float*)d_in[0];
    const int*   ei    = (const int*)d_in[1];
    const int*   batch = (const int*)d_in[2];
    const float* W1    = (const float*)d_in[3];
    const float* b1    = (const float*)d_in[4];
    const float* W2    = (const float*)d_in[5];
    const float* b2    = (const float*)d_in[6];
    const float* fcW   = (const float*)d_in[7];
    const float* fcb   = (const float*)d_in[8];
    float* out = (float*)d_out;

    const int T = 256;
    // bucketed CSR build (g_cur arrives zeroed: module init or previous k_final)
    k_fill<<<(EE + T - 1) / T, T>>>(ei, batch);

    // layer 1 (two nodes per warp -> NN/2 warps)
    k_gather<0><<<((NN / 2) * 32 + T - 1) / T, T>>>(x);
    k_gemm1<<<(NN + T - 1) / T, T>>>(W1, b1);

    // layer 2 (+ fused fc/pool)
    k_gather<1><<<((NN / 2) * 32 + T - 1) / T, T>>>(nullptr);
    k_gemm2_fused<<<(NN + 127) / 128, 128>>>(W2, b2, fcW, batch);

    k_final<<<(NN + T - 1) / T, T>>>(out, fcb);
}

// round 14
// speedup vs baseline: 1.0484x; 1.0484x over previous
#include <cuda_runtime.h>
#include <cuda_fp16.h>

#define NN 50000
#define EE 800000
#define FF 64
#define GG 128
#define CAP 96   // per-node bucket capacity (Poisson λ=16 -> P(deg>96) ~ 0)

// ---------------- device scratch (static allocation only) --------------------
// Zero-initialized at module load; k_final re-zeroes mutable state after every
// call so each graph replay starts clean (deterministic).
__device__ int   g_cur[NN];                 // per-node fill cursor == in-degree
__device__ int   g_src[NN * CAP];           // bucketed CSR: sources per dst
__device__ __align__(16) __half g_xh[NN * FF];   // fp16 copy of x
__device__ __align__(16) __half g_h1h[NN * FF];  // fp16 h1
__device__ __align__(16) float g_agg[NN * FF];   // fp32 aggregation (GEMM input)
__device__ float g_pool[GG];
__device__ float g_cnt[GG];
__device__ int   g_b64;

__device__ __forceinline__ int loadIdx(const int* p, long long i, int is64) {
    return is64 ? p[2 * i] : p[(int)i];
}

__device__ __forceinline__ int detect_ei64(const int* ei) {
    int or_odd = 0;
    #pragma unroll
    for (int k = 0; k < 8; k++) or_odd |= ei[2 * k + 1];
    return (or_odd == 0) ? 1 : 0;
}

// ---------------- fill: bucketed CSR build + x->fp16; block 0: batch work ----
__global__ void k_fill(const int* ei, const int* batch, const float* __restrict__ x) {
    int is64 = detect_ei64(ei);
    int e = blockIdx.x * blockDim.x + threadIdx.x;
    if (e < EE) {
        int s = loadIdx(ei, e, is64);
        int d = loadIdx(ei, (long long)EE + e, is64);
        int pos = atomicAdd(&g_cur[d], 1);
        if (pos < CAP) g_src[d * CAP + pos] = s;   // clamp guards OOB
        // EE == NN*FF/4 exactly: thread e converts float4 slot e of x to fp16
        float4 v = reinterpret_cast<const float4*>(x)[e];
        __half2 h0 = __floats2half2_rn(v.x, v.y);
        __half2 h1 = __floats2half2_rn(v.z, v.w);
        uint2 pk;
        pk.x = *reinterpret_cast<unsigned*>(&h0);
        pk.y = *reinterpret_cast<unsigned*>(&h1);
        reinterpret_cast<uint2*>(g_xh)[e] = pk;
    }
    if (blockIdx.x == 0) {
        int t = threadIdx.x;
        __shared__ int s_b64;
        if (t == 0) {
            int or_tail = 0;
            #pragma unroll
            for (int k = 0; k < 8; k++) or_tail |= batch[NN - 1 - 2 * k];
            s_b64 = (or_tail == 0) ? 1 : 0;
            g_b64 = s_b64;
        }
        __syncthreads();
        int isb = s_b64;
        if (t < GG) {
            int lo0 = 0, hi0 = NN, lo1 = 0, hi1 = NN;
            while (lo0 < hi0) { int m = (lo0 + hi0) >> 1; if (loadIdx(batch, m, isb) < t)     lo0 = m + 1; else hi0 = m; }
            while (lo1 < hi1) { int m = (lo1 + hi1) >> 1; if (loadIdx(batch, m, isb) < t + 1) lo1 = m + 1; else hi1 = m; }
            g_cnt[t] = (float)(lo1 - lo0);
        }
    }
}

// gather: one WARP per node, half2 per lane (32 x 4B = full 128B fp16 row).
// Per edge: 2 SHFL + 1 LDG.32 + cvt + 2 FMA; fp32 accumulation.
// agg[d] = dinv[d] * ( dinv[d]*feat[d] + sum_e dinv[src]*feat[src] ),
// dinv[n] = rsqrt(deg[n]+1) from g_cur.
template <int LAYER>
__global__ void k_gather() {
    const __half2* feath = reinterpret_cast<const __half2*>(
        (LAYER == 0) ? g_xh : g_h1h);
    int node = (blockIdx.x * blockDim.x + threadIdx.x) >> 5;
    if (node >= NN) return;
    int lane = threadIdx.x & 31;

    int deg = min(g_cur[node], CAP);
    float dd = rsqrtf((float)(deg + 1));
    float2 v = __half22float2(feath[node * 32 + lane]);
    float2 acc = make_float2(v.x * dd, v.y * dd);

    int row = node * CAP;
    for (int base = 0; base < deg; base += 32) {
        int cnt = min(deg - base, 32);
        int sl = 0; float wl = 0.f;
        if (lane < cnt) {
            sl = __ldg(&g_src[row + base + lane]);
            wl = rsqrtf((float)(__ldg(&g_cur[sl]) + 1));
        }
        #pragma unroll 8
        for (int j = 0; j < cnt; j++) {
            int   s = __shfl_sync(0xffffffffu, sl, j);
            float w = __shfl_sync(0xffffffffu, wl, j);
            float2 f = __half22float2(feath[s * 32 + lane]);
            acc.x = fmaf(w, f.x, acc.x);
            acc.y = fmaf(w, f.y, acc.y);
        }
    }
    reinterpret_cast<float2*>(g_agg)[node * 32 + lane] =
        make_float2(acc.x * dd, acc.y * dd);
}

// h1 = relu(agg @ W1 + b1) -> stored as fp16,  W1: [64,64]
__global__ void k_gemm1(const float* __restrict__ W1, const float* __restrict__ b1) {
    __shared__ __align__(16) float Ws[FF * FF];
    __shared__ __align__(16) float bs[FF];
    int tid = threadIdx.x;
    for (int k = tid; k < FF * FF; k += blockDim.x) Ws[k] = W1[k];
    if (tid < FF) bs[tid] = b1[tid];
    __syncthreads();

    int i = blockIdx.x * blockDim.x + tid;
    if (i >= NN) return;

    float a[FF];
    #pragma unroll
    for (int k4 = 0; k4 < FF / 4; k4++) {
        float4 v = reinterpret_cast<const float4*>(g_agg)[i * (FF / 4) + k4];
        a[4 * k4 + 0] = v.x; a[4 * k4 + 1] = v.y; a[4 * k4 + 2] = v.z; a[4 * k4 + 3] = v.w;
    }
    const float4* Ws4 = reinterpret_cast<const float4*>(Ws);
    const float4* bs4 = reinterpret_cast<const float4*>(bs);
    #pragma unroll
    for (int j4 = 0; j4 < FF / 4; j4++) {
        float4 acc = bs4[j4];
        #pragma unroll 16
        for (int k = 0; k < FF; k++) {
            float4 w = Ws4[k * (FF / 4) + j4];
            acc.x = fmaf(a[k], w.x, acc.x);
            acc.y = fmaf(a[k], w.y, acc.y);
            acc.z = fmaf(a[k], w.z, acc.z);
            acc.w = fmaf(a[k], w.w, acc.w);
        }
        acc.x = fmaxf(acc.x, 0.0f); acc.y = fmaxf(acc.y, 0.0f);
        acc.z = fmaxf(acc.z, 0.0f); acc.w = fmaxf(acc.w, 0.0f);
        __half2 h0 = __floats2half2_rn(acc.x, acc.y);
        __half2 h1 = __floats2half2_rn(acc.z, acc.w);
        uint2 pk;
        pk.x = *reinterpret_cast<unsigned*>(&h0);
        pk.y = *reinterpret_cast<unsigned*>(&h1);
        reinterpret_cast<uint2*>(g_h1h)[i * (FF / 4) + j4] = pk;
    }
}

// fused: s_i = relu(agg_i @ W2 + b2) . fcW ; pool[batch[i]] += s_i (warp-aggregated)
__global__ void k_gemm2_fused(const float* __restrict__ W2, const float* __restrict__ b2,
                              const float* __restrict__ fcW, const int* __restrict__ batch) {
    __shared__ __align__(16) float Ws[FF * 2 * FF];   // 32 KB
    __shared__ __align__(16) float bs[2 * FF];
    __shared__ __align__(16) float fs[2 * FF];
    int tid = threadIdx.x;
    for (int k = tid; k < FF * 2 * FF; k += blockDim.x) Ws[k] = W2[k];
    for (int k = tid; k < 2 * FF; k += blockDim.x) { bs[k] = b2[k]; fs[k] = fcW[k]; }
    __syncthreads();

    int i = blockIdx.x * blockDim.x + tid;
    float s = 0.0f;
    int g = -1;
    if (i < NN) {
        g = loadIdx(batch, i, g_b64);
        float a[FF];
        #pragma unroll
        for (int k4 = 0; k4 < FF / 4; k4++) {
            float4 v = reinterpret_cast<const float4*>(g_agg)[i * (FF / 4) + k4];
            a[4 * k4 + 0] = v.x; a[4 * k4 + 1] = v.y; a[4 * k4 + 2] = v.z; a[4 * k4 + 3] = v.w;
        }
        const float4* Ws4 = reinterpret_cast<const float4*>(Ws);
        const float4* bs4 = reinterpret_cast<const float4*>(bs);
        const float4* fs4 = reinterpret_cast<const float4*>(fs);
        #pragma unroll 4
        for (int j4 = 0; j4 < (2 * FF) / 4; j4++) {
            float4 acc = bs4[j4];
            #pragma unroll 16
            for (int k = 0; k < FF; k++) {
                float4 w = Ws4[k * (2 * FF / 4) + j4];
                acc.x = fmaf(a[k], w.x, acc.x);
                acc.y = fmaf(a[k], w.y, acc.y);
                acc.z = fmaf(a[k], w.z, acc.z);
                acc.w = fmaf(a[k], w.w, acc.w);
            }
            acc.x = fmaxf(acc.x, 0.0f); acc.y = fmaxf(acc.y, 0.0f);
            acc.z = fmaxf(acc.z, 0.0f); acc.w = fmaxf(acc.w, 0.0f);
            float4 f = fs4[j4];
            s = fmaf(acc.x, f.x, s); s = fmaf(acc.y, f.y, s);
            s = fmaf(acc.z, f.z, s); s = fmaf(acc.w, f.w, s);
        }
    }
    unsigned lane = threadIdx.x & 31u;
    #pragma unroll
    for (int off = 1; off < 32; off <<= 1) {
        float o = __shfl_down_sync(0xffffffffu, s, off);
        int   og = __shfl_down_sync(0xffffffffu, g, off);
        if (lane + off < 32 && og == g) s += o;
    }
    int gprev = __shfl_up_sync(0xffffffffu, g, 1);
    if (g >= 0 && (lane == 0 || gprev != g)) atomicAdd(&g_pool[g], s);
}

// final: block 0 writes output; ALL blocks reset mutable state for next replay
__global__ void k_final(float* __restrict__ out, const float* __restrict__ fcb) {
    int i = blockIdx.x * blockDim.x + threadIdx.x;
    if (blockIdx.x == 0 && threadIdx.x < GG) {
        int t = threadIdx.x;
        out[t] = g_pool[t] / fmaxf(g_cnt[t], 1.0f) + fcb[0];
        g_pool[t] = 0.0f;   // after read
    }
    if (i < NN) g_cur[i] = 0;
}

// ---------------- launch ------------------------------------------------------
extern "C" void kernel_launch(void* const* d_in, const int* in_sizes, int n_in,
                              void* d_out, int out_size) {
    const float* x     = (const float*)d_in[0];
    const int*   ei    = (const int*)d_in[1];
    const int*   batch = (const int*)d_in[2];
    const float* W1    = (const float*)d_in[3];
    const float* b1    = (const float*)d_in[4];
    const float* W2    = (const float*)d_in[5];
    const float* b2    = (const float*)d_in[6];
    const float* fcW   = (const float*)d_in[7];
    const float* fcb   = (const float*)d_in[8];
    float* out = (float*)d_out;

    const int T = 256;
    // bucketed CSR build + x->fp16 (g_cur arrives zeroed)
    k_fill<<<(EE + T - 1) / T, T>>>(ei, batch, x);

    // layer 1 (warp per node, fp16 features)
    k_gather<0><<<(NN * 32) / T, T>>>();
    k_gemm1<<<(NN + T - 1) / T, T>>>(W1, b1);

    // layer 2 (+ fused fc/pool)
    k_gather<1><<<(NN * 32) / T, T>>>();
    k_gemm2_fused<<<(NN + T - 1) / T, T>>>(W2, b2, fcW, batch);

    k_final<<<(NN + T - 1) / T, T>>>(out, fcb);
}

// round 16
// speedup vs baseline: 1.1199x; 1.0682x over previous
#include <cuda_runtime.h>
#include <cuda_fp16.h>

#define NN 50000
#define EE 800000
#define FF 64
#define GG 128
#define CAP 96   // per-node bucket capacity (Poisson λ=16 -> P(deg>96) ~ 0)

// ---------------- device scratch (static allocation only) --------------------
// Zero-initialized at module load; kernels reset mutable state each call so
// every graph replay starts clean (deterministic).
__device__ int   g_cur[NN];                 // per-node fill cursor == in-degree
__device__ int   g_src[NN * CAP];           // bucketed CSR: sources per dst
__device__ __align__(16) __half g_u0[NN * FF];   // fp16 u = dinv * x
__device__ __align__(16) __half g_u1[NN * FF];   // fp16 u1 = dinv * h1
__device__ __align__(16) float g_agg[NN * FF];   // fp32 aggregation (GEMM input)
__device__ float g_pool[GG];
__device__ float g_cnt[GG];
__device__ int   g_b64;
__device__ int   g_tick;                    // gemm2 completion ticket

__device__ __forceinline__ int loadIdx(const int* p, long long i, int is64) {
    return is64 ? p[2 * i] : p[(int)i];
}

__device__ __forceinline__ int detect_ei64(const int* ei) {
    int or_odd = 0;
    #pragma unroll
    for (int k = 0; k < 8; k++) or_odd |= ei[2 * k + 1];
    return (or_odd == 0) ? 1 : 0;
}

// ---------------- fill: bucketed CSR build; block 0: batch dtype + counts ----
__global__ void k_fill(const int* ei, const int* batch) {
    int is64 = detect_ei64(ei);
    int e = blockIdx.x * blockDim.x + threadIdx.x;
    if (e < EE) {
        int s = loadIdx(ei, e, is64);
        int d = loadIdx(ei, (long long)EE + e, is64);
        int pos = atomicAdd(&g_cur[d], 1);
        if (pos < CAP) g_src[d * CAP + pos] = s;   // clamp guards OOB
    }
    if (blockIdx.x == 0) {
        int t = threadIdx.x;
        __shared__ int s_b64;
        if (t == 0) {
            int or_tail = 0;
            #pragma unroll
            for (int k = 0; k < 8; k++) or_tail |= batch[NN - 1 - 2 * k];
            s_b64 = (or_tail == 0) ? 1 : 0;
            g_b64 = s_b64;
        }
        __syncthreads();
        int isb = s_b64;
        if (t < GG) {
            int lo0 = 0, hi0 = NN, lo1 = 0, hi1 = NN;
            while (lo0 < hi0) { int m = (lo0 + hi0) >> 1; if (loadIdx(batch, m, isb) < t)     lo0 = m + 1; else hi0 = m; }
            while (lo1 < hi1) { int m = (lo1 + hi1) >> 1; if (loadIdx(batch, m, isb) < t + 1) lo1 = m + 1; else hi1 = m; }
            g_cnt[t] = (float)(lo1 - lo0);
        }
    }
}

// scale: u0 = dinv[node] * x  (fp16). One thread per float4 slot (NN*16).
__global__ void k_scale(const float* __restrict__ x) {
    int sidx = blockIdx.x * blockDim.x + threadIdx.x;
    if (sidx >= NN * (FF / 4)) return;
    int node = sidx >> 4;
    float dd = rsqrtf((float)(min(g_cur[node], CAP) + 1));
    float4 v = reinterpret_cast<const float4*>(x)[sidx];
    __half2 h0 = __floats2half2_rn(v.x * dd, v.y * dd);
    __half2 h1 = __floats2half2_rn(v.z * dd, v.w * dd);
    uint2 pk;
    pk.x = *reinterpret_cast<unsigned*>(&h0);
    pk.y = *reinterpret_cast<unsigned*>(&h1);
    reinterpret_cast<uint2*>(g_u0)[sidx] = pk;
}

// gather: one WARP per node, half2 per lane. UNWEIGHTED inner sum:
// agg[d] = dinv[d] * ( u[d] + sum_e u[src_e] )   (features pre-scaled by dinv)
// Per edge: 1 SHFL + 1 LDG.32 + cvt + 2 FADD.
template <int LAYER>
__global__ void k_gather() {
    const __half2* feath = reinterpret_cast<const __half2*>(
        (LAYER == 0) ? g_u0 : g_u1);
    int node = (blockIdx.x * blockDim.x + threadIdx.x) >> 5;
    if (node >= NN) return;
    int lane = threadIdx.x & 31;

    int deg = min(g_cur[node], CAP);
    float dd = rsqrtf((float)(deg + 1));
    float2 acc = __half22float2(feath[node * 32 + lane]);   // u[d]

    int row = node * CAP;
    for (int base = 0; base < deg; base += 32) {
        int cnt = min(deg - base, 32);
        int sl = 0;
        if (lane < cnt) sl = __ldg(&g_src[row + base + lane]);
        #pragma unroll 8
        for (int j = 0; j < cnt; j++) {
            int s = __shfl_sync(0xffffffffu, sl, j);
            float2 f = __half22float2(feath[s * 32 + lane]);
            acc.x += f.x;
            acc.y += f.y;
        }
    }
    reinterpret_cast<float2*>(g_agg)[node * 32 + lane] =
        make_float2(acc.x * dd, acc.y * dd);
}

// h1 = relu(agg @ W1 + b1); store u1 = dinv * h1 as fp16.  W1: [64,64]
__global__ void k_gemm1(const float* __restrict__ W1, const float* __restrict__ b1) {
    __shared__ __align__(16) float Ws[FF * FF];
    __shared__ __align__(16) float bs[FF];
    int tid = threadIdx.x;
    for (int k = tid; k < FF * FF; k += blockDim.x) Ws[k] = W1[k];
    if (tid < FF) bs[tid] = b1[tid];
    __syncthreads();

    int i = blockIdx.x * blockDim.x + tid;
    if (i >= NN) return;

    float dd = rsqrtf((float)(min(g_cur[i], CAP) + 1));

    float a[FF];
    #pragma unroll
    for (int k4 = 0; k4 < FF / 4; k4++) {
        float4 v = reinterpret_cast<const float4*>(g_agg)[i * (FF / 4) + k4];
        a[4 * k4 + 0] = v.x; a[4 * k4 + 1] = v.y; a[4 * k4 + 2] = v.z; a[4 * k4 + 3] = v.w;
    }
    const float4* Ws4 = reinterpret_cast<const float4*>(Ws);
    const float4* bs4 = reinterpret_cast<const float4*>(bs);
    #pragma unroll
    for (int j4 = 0; j4 < FF / 4; j4++) {
        float4 acc = bs4[j4];
        #pragma unroll 16
        for (int k = 0; k < FF; k++) {
            float4 w = Ws4[k * (FF / 4) + j4];
            acc.x = fmaf(a[k], w.x, acc.x);
            acc.y = fmaf(a[k], w.y, acc.y);
            acc.z = fmaf(a[k], w.z, acc.z);
            acc.w = fmaf(a[k], w.w, acc.w);
        }
        acc.x = fmaxf(acc.x, 0.0f) * dd; acc.y = fmaxf(acc.y, 0.0f) * dd;
        acc.z = fmaxf(acc.z, 0.0f) * dd; acc.w = fmaxf(acc.w, 0.0f) * dd;
        __half2 h0 = __floats2half2_rn(acc.x, acc.y);
        __half2 h1 = __floats2half2_rn(acc.z, acc.w);
        uint2 pk;
        pk.x = *reinterpret_cast<unsigned*>(&h0);
        pk.y = *reinterpret_cast<unsigned*>(&h1);
        reinterpret_cast<uint2*>(g_u1)[i * (FF / 4) + j4] = pk;
    }
}

// fused: s_i = relu(agg_i @ W2 + b2) . fcW ; pool[batch[i]] += s_i; last block
// writes the final output (ticket) and resets pool/tick; all blocks reset g_cur.
__global__ void k_gemm2_fused(const float* __restrict__ W2, const float* __restrict__ b2,
                              const float* __restrict__ fcW, const int* __restrict__ batch,
                              float* __restrict__ out, const float* __restrict__ fcb) {
    __shared__ __align__(16) float Ws[FF * 2 * FF];   // 32 KB
    __shared__ __align__(16) float bs[2 * FF];
    __shared__ __align__(16) float fs[2 * FF];
    int tid = threadIdx.x;
    for (int k = tid; k < FF * 2 * FF; k += blockDim.x) Ws[k] = W2[k];
    for (int k = tid; k < 2 * FF; k += blockDim.x) { bs[k] = b2[k]; fs[k] = fcW[k]; }

    int i = blockIdx.x * blockDim.x + tid;
    if (i < NN) g_cur[i] = 0;      // reset for next replay (last user was gemm1)
    __syncthreads();

    float s = 0.0f;
    int g = -1;
    if (i < NN) {
        g = loadIdx(batch, i, g_b64);
        float a[FF];
        #pragma unroll
        for (int k4 = 0; k4 < FF / 4; k4++) {
            float4 v = reinterpret_cast<const float4*>(g_agg)[i * (FF / 4) + k4];
            a[4 * k4 + 0] = v.x; a[4 * k4 + 1] = v.y; a[4 * k4 + 2] = v.z; a[4 * k4 + 3] = v.w;
        }
        const float4* Ws4 = reinterpret_cast<const float4*>(Ws);
        const float4* bs4 = reinterpret_cast<const float4*>(bs);
        const float4* fs4 = reinterpret_cast<const float4*>(fs);
        #pragma unroll 4
        for (int j4 = 0; j4 < (2 * FF) / 4; j4++) {
            float4 acc = bs4[j4];
            #pragma unroll 16
            for (int k = 0; k < FF; k++) {
                float4 w = Ws4[k * (2 * FF / 4) + j4];
                acc.x = fmaf(a[k], w.x, acc.x);
                acc.y = fmaf(a[k], w.y, acc.y);
                acc.z = fmaf(a[k], w.z, acc.z);
                acc.w = fmaf(a[k], w.w, acc.w);
            }
            acc.x = fmaxf(acc.x, 0.0f); acc.y = fmaxf(acc.y, 0.0f);
            acc.z = fmaxf(acc.z, 0.0f); acc.w = fmaxf(acc.w, 0.0f);
            float4 f = fs4[j4];
            s = fmaf(acc.x, f.x, s); s = fmaf(acc.y, f.y, s);
            s = fmaf(acc.z, f.z, s); s = fmaf(acc.w, f.w, s);
        }
    }
    unsigned lane = threadIdx.x & 31u;
    #pragma unroll
    for (int off = 1; off < 32; off <<= 1) {
        float o = __shfl_down_sync(0xffffffffu, s, off);
        int   og = __shfl_down_sync(0xffffffffu, g, off);
        if (lane + off < 32 && og == g) s += o;
    }
    int gprev = __shfl_up_sync(0xffffffffu, g, 1);
    if (g >= 0 && (lane == 0 || gprev != g)) atomicAdd(&g_pool[g], s);

    // last-block ticket: write final output after ALL pool atomics are visible
    __threadfence();
    __shared__ bool isLast;
    __syncthreads();
    if (tid == 0) isLast = (atomicAdd(&g_tick, 1) == (int)gridDim.x - 1);
    __syncthreads();
    if (isLast) {
        if (tid < GG) {
            out[tid] = g_pool[tid] / fmaxf(g_cnt[tid], 1.0f) + fcb[0];
            g_pool[tid] = 0.0f;
        }
        if (tid == 0) g_tick = 0;
    }
}

// ---------------- launch ------------------------------------------------------
extern "C" void kernel_launch(void* const* d_in, const int* in_sizes, int n_in,
                              void* d_out, int out_size) {
    const float* x     = (const float*)d_in[0];
    const int*   ei    = (const int*)d_in[1];
    const int*   batch = (const int*)d_in[2];
    const float* W1    = (const float*)d_in[3];
    const float* b1    = (const float*)d_in[4];
    const float* W2    = (const float*)d_in[5];
    const float* b2    = (const float*)d_in[6];
    const float* fcW   = (const float*)d_in[7];
    const float* fcb   = (const float*)d_in[8];
    float* out = (float*)d_out;

    const int T = 256;
    // bucketed CSR build (g_cur arrives zeroed: module init or previous gemm2)
    k_fill<<<(EE + T - 1) / T, T>>>(ei, batch);
    // u0 = dinv * x (fp16), after degrees are final
    k_scale<<<(NN * (FF / 4) + T - 1) / T, T>>>(x);

    // layer 1 (warp per node, unweighted fp16 gather)
    k_gather<0><<<(NN * 32) / T, T>>>();
    k_gemm1<<<(NN + T - 1) / T, T>>>(W1, b1);

    // layer 2 (+ fused fc/pool/final)
    k_gather<1><<<(NN * 32) / T, T>>>();
    k_gemm2_fused<<<(NN + T - 1) / T, T>>>(W2, b2, fcW, batch, out, fcb);
}